// round 1
// baseline (speedup 1.0000x reference)
#include <cuda_runtime.h>
#include <cuda_bf16.h>

#define TT   32
#define BB   16
#define INS  64
#define OUTS 64
#define LL   4096
#define WW   64
#define CO   332      // OUT + 70 + 198
#define NBLK 128
#define NTHR 256

// ---------------- persistent device state (no allocs allowed) ----------------
__device__ float g_mem[BB*LL*WW];     // 16 MB memory matrix
__device__ float g_wr [BB*LL];        // read weights (normalized, prev step)
__device__ float g_ww [BB*LL];        // write weights
__device__ float g_wcr[BB*LL];        // exp(K*beta - beta) read head
__device__ float g_wcw[BB*LL];        // exp(K*beta - beta) write head
__device__ float g_wur[BB*LL];        // sharpened unnormalized read w
__device__ float g_wuw[BB*LL];        // sharpened unnormalized write w
__device__ float g_coX[TT*BB*CO];     // precomputed x @ Wc[:64] + bc
__device__ float g_params[BB*288];    // per-batch per-step packed params
__device__ float g_out[BB*OUTS];
__device__ float g_r  [BB*WW];
__device__ float g_sums[BB*4];        // [sum_exp_r, sum_exp_w, sum_wr, sum_ww]
__device__ unsigned int g_bar_count = 0;
__device__ unsigned int g_bar_gen   = 0;

__device__ __forceinline__ float softplusf(float x) {
    return (x > 20.f) ? x : log1pf(__expf(x));
}
__device__ __forceinline__ float sigmoidf(float x) {
    return 1.f / (1.f + __expf(-x));
}

// Sense-reversal grid barrier. Replay-safe: count returns to 0 at every
// barrier, gen is read fresh each time (monotonic across graph replays).
__device__ __forceinline__ void gridbar() {
    __syncthreads();
    if (threadIdx.x == 0) {
        __threadfence();                               // release
        unsigned int gen  = *(volatile unsigned int*)&g_bar_gen;
        unsigned int prev = atomicAdd(&g_bar_count, 1u);
        if (prev == gridDim.x - 1u) {
            atomicExch(&g_bar_count, 0u);
            __threadfence();
            atomicAdd(&g_bar_gen, 1u);
        } else {
            while (*(volatile unsigned int*)&g_bar_gen == gen) { }
        }
        __threadfence();                               // acquire
    }
    __syncthreads();
}

__global__ __launch_bounds__(NTHR)
void ntm_kernel(const float* __restrict__ x, const float* __restrict__ Wc,
                const float* __restrict__ bc, float* __restrict__ dout)
{
    const int bk   = blockIdx.x;
    const int tid  = threadIdx.x;
    const int gthr = bk * NTHR + tid;
    const int GT   = NBLK * NTHR;
    __shared__ __align__(16) float sh[768];

    // ---------------- init: zero state + precompute x-part of controller ----
    {
        float4* m4 = (float4*)g_mem;
        for (int i = gthr; i < BB*LL*WW/4; i += GT) m4[i] = make_float4(0,0,0,0);
        for (int i = gthr; i < BB*LL; i += GT) {
            float v = ((i & (LL-1)) == 0) ? 1.f : 0.f;   // delta at l=0
            g_wr[i] = v; g_ww[i] = v;
        }
        if (gthr < BB*OUTS) g_out[gthr] = 0.f;
        if (gthr < BB*WW)   g_r  [gthr] = 0.f;
        for (int idx = gthr; idx < TT*BB*CO; idx += GT) {
            int j  = idx % CO;
            int tb = idx / CO;
            const float* xp = x + tb * INS;
            float acc = bc[j];
            #pragma unroll 8
            for (int i = 0; i < INS; i++) acc = fmaf(xp[i], Wc[i*CO + j], acc);
            g_coX[idx] = acc;
        }
    }
    gridbar();

    const int b2   = bk >> 3;           // batch handled in phases 2-4
    const int l0   = (bk & 7) * 512;    // 512-row chunk of L
    const int warp = tid >> 5;
    const int lane = tid & 31;

    for (int t = 0; t < TT; ++t) {
        // -------- Phase 1: controller + param derivation (blocks 0..15) ----
        if (bk < BB) {
            const int b = bk;
            float* cat  = sh;          // [out(64), r(64)]
            float* co   = sh + 128;    // 332 controller outputs
            float* scal = sh + 464;
            if (tid < 64)       cat[tid] = g_out[b*OUTS + tid];
            else if (tid < 128) cat[tid] = __ldcg(&g_r[b*WW + tid - 64]);
            __syncthreads();
            const float* wbase = Wc + INS*CO;   // rows 64..191
            for (int j = tid; j < CO; j += NTHR) {
                float acc = g_coX[(t*BB + b)*CO + j];
                #pragma unroll 16
                for (int i = 0; i < 128; i++)
                    acc = fmaf(cat[i], wbase[i*CO + j], acc);
                co[j] = acc;
            }
            __syncthreads();
            if (warp == 0) {           // ||k_r||^2
                float p = co[64+lane]*co[64+lane] + co[96+lane]*co[96+lane];
                #pragma unroll
                for (int o = 16; o; o >>= 1) p += __shfl_xor_sync(0xffffffffu, p, o);
                if (lane == 0) scal[14] = p;
            } else if (warp == 1) {    // ||k_w||^2
                float p = co[134+lane]*co[134+lane] + co[166+lane]*co[166+lane];
                #pragma unroll
                for (int o = 16; o; o >>= 1) p += __shfl_xor_sync(0xffffffffu, p, o);
                if (lane == 0) scal[15] = p;
            }
            __syncthreads();
            float* P = g_params + b*288;
            if (tid == 0) {
                float beta_r = softplusf(co[128]);
                float beta_w = softplusf(co[198]);
                scal[0] = beta_r * rsqrtf(scal[14] + 1e-14f);  // beta/||k_r||
                scal[1] = beta_w * rsqrtf(scal[15] + 1e-14f);
                P[128] = beta_r;
                P[129] = sigmoidf(co[129]);
                P[130] = softplusf(co[130]) + 1.f;
                float m = fmaxf(co[131], fmaxf(co[132], co[133]));
                float e0=__expf(co[131]-m), e1=__expf(co[132]-m), e2=__expf(co[133]-m);
                float inv = 1.f/(e0+e1+e2);
                P[131]=e0*inv; P[132]=e1*inv; P[133]=e2*inv;
                P[134] = beta_w;
                P[135] = sigmoidf(co[199]);
                P[136] = softplusf(co[200]) + 1.f;
                m = fmaxf(co[201], fmaxf(co[202], co[203]));
                e0=__expf(co[201]-m); e1=__expf(co[202]-m); e2=__expf(co[203]-m);
                inv = 1.f/(e0+e1+e2);
                P[137]=e0*inv; P[138]=e1*inv; P[139]=e2*inv;
            }
            __syncthreads();
            if (tid < 64) {
                P[tid]       = co[64 + tid]  * scal[0];   // k_r * beta/||k_r||
                P[64 + tid]  = co[134 + tid] * scal[1];   // k_w * beta/||k_w||
                P[140 + tid] = sigmoidf(co[204 + tid]);   // e
                P[204 + tid] = co[268 + tid];             // a
                float o = co[tid];
                g_out[b*OUTS + tid] = o;
                dout[(t*BB + b)*OUTS + tid] = o;          // emit output
                g_r[b*WW + tid] = 0.f;                    // reset accumulator
            }
            if (tid < 4) g_sums[b*4 + tid] = 0.f;
        }
        gridbar();

        // -------- Phase 2: cosine similarity over memory rows --------------
        {
            const float* P = g_params + b2*288;
            if (tid < 128) sh[tid] = __ldcg(&P[tid]);
            __syncthreads();
            const float beta_r = __ldcg(&P[128]);
            const float beta_w = __ldcg(&P[134]);
            const float2 kr = ((const float2*)sh)[lane];
            const float2 kw = ((const float2*)(sh + 64))[lane];
            float s_er = 0.f, s_ew = 0.f;
            const int base = b2*LL + l0 + warp*64;
            #pragma unroll 4
            for (int k = 0; k < 64; ++k) {
                const int row = base + k;
                const float2 m = ((const float2*)g_mem)[row*32 + lane];
                float dr = m.x*kr.x + m.y*kr.y;
                float dw = m.x*kw.x + m.y*kw.y;
                float ds = m.x*m.x + m.y*m.y;
                #pragma unroll
                for (int o = 16; o; o >>= 1) {
                    dr += __shfl_xor_sync(0xffffffffu, dr, o);
                    dw += __shfl_xor_sync(0xffffffffu, dw, o);
                    ds += __shfl_xor_sync(0xffffffffu, ds, o);
                }
                if (lane == 0) {
                    const float inm = rsqrtf(ds + 1e-14f);
                    // softmax shifted by beta: arg in [-2*beta, 0], overflow-safe
                    const float er = __expf(dr*inm - beta_r);
                    const float ew = __expf(dw*inm - beta_w);
                    g_wcr[row] = er; g_wcw[row] = ew;
                    s_er += er; s_ew += ew;
                }
            }
            __syncthreads();
            if (lane == 0) { sh[128 + warp] = s_er; sh[136 + warp] = s_ew; }
            __syncthreads();
            if (tid == 0) {
                float a = 0.f, c = 0.f;
                #pragma unroll
                for (int i = 0; i < 8; ++i) { a += sh[128+i]; c += sh[136+i]; }
                atomicAdd(&g_sums[b2*4 + 0], a);
                atomicAdd(&g_sums[b2*4 + 1], c);
            }
        }
        gridbar();

        // -------- Phase 3: gate + circular shift + sharpen -----------------
        {
            const float* P = g_params + b2*288;
            const float inv_ser = 1.f / __ldcg(&g_sums[b2*4 + 0]);
            const float inv_sew = 1.f / __ldcg(&g_sums[b2*4 + 1]);
            const float gr  = __ldcg(&P[129]), gamr = __ldcg(&P[130]);
            const float sr0 = __ldcg(&P[131]), sr1 = __ldcg(&P[132]), sr2 = __ldcg(&P[133]);
            const float gw  = __ldcg(&P[135]), gamw = __ldcg(&P[136]);
            const float sw0 = __ldcg(&P[137]), sw1 = __ldcg(&P[138]), sw2 = __ldcg(&P[139]);
            const int bl = b2 * LL;
            float ps_r = 0.f, ps_w = 0.f;
            for (int k = tid; k < 512; k += NTHR) {
                const int l  = l0 + k;
                const int lm = bl + ((l + LL - 1) & (LL - 1));
                const int lc = bl + l;
                const int lp = bl + ((l + 1) & (LL - 1));
                // read head
                float wgm = __ldcg(&g_wcr[lm])*inv_ser*gr + (1.f-gr)*__ldcg(&g_wr[lm]);
                float wgc = __ldcg(&g_wcr[lc])*inv_ser*gr + (1.f-gr)*__ldcg(&g_wr[lc]);
                float wgp = __ldcg(&g_wcr[lp])*inv_ser*gr + (1.f-gr)*__ldcg(&g_wr[lp]);
                float wu  = powf(fmaxf(sr0*wgm + sr1*wgc + sr2*wgp, 0.f), gamr);
                g_wur[lc] = wu; ps_r += wu;
                // write head
                wgm = __ldcg(&g_wcw[lm])*inv_sew*gw + (1.f-gw)*__ldcg(&g_ww[lm]);
                wgc = __ldcg(&g_wcw[lc])*inv_sew*gw + (1.f-gw)*__ldcg(&g_ww[lc]);
                wgp = __ldcg(&g_wcw[lp])*inv_sew*gw + (1.f-gw)*__ldcg(&g_ww[lp]);
                wu  = powf(fmaxf(sw0*wgm + sw1*wgc + sw2*wgp, 0.f), gamw);
                g_wuw[lc] = wu; ps_w += wu;
            }
            __syncthreads();
            sh[tid] = ps_r; sh[256 + tid] = ps_w;
            __syncthreads();
            for (int s = 128; s; s >>= 1) {
                if (tid < s) { sh[tid] += sh[tid+s]; sh[256+tid] += sh[256+tid+s]; }
                __syncthreads();
            }
            if (tid == 0) {
                atomicAdd(&g_sums[b2*4 + 2], sh[0]);
                atomicAdd(&g_sums[b2*4 + 3], sh[256]);
            }
        }
        gridbar();

        // -------- Phase 4: read vector + erase/add memory update -----------
        {
            const float* P = g_params + b2*288;
            const float inv_sr = 1.f / __ldcg(&g_sums[b2*4 + 2]);
            const float inv_sw = 1.f / __ldcg(&g_sums[b2*4 + 3]);
            if (tid < 128) sh[tid] = __ldcg(&P[140 + tid]);  // e | a
            __syncthreads();
            const float2 e2 = ((const float2*)sh)[lane];
            const float2 a2 = ((const float2*)(sh + 64))[lane];
            float rx = 0.f, ry = 0.f;
            const int base = b2*LL + l0 + warp*64;
            #pragma unroll 2
            for (int k = 0; k < 64; ++k) {
                const int row = base + k;
                const float wrv = g_wur[row] * inv_sr;
                const float wwv = g_wuw[row] * inv_sw;
                if (lane == 0) { g_wr[row] = wrv; g_ww[row] = wwv; }
                float2* mp = ((float2*)g_mem) + row*32 + lane;
                float2 m = *mp;
                rx = fmaf(m.x, wrv, rx);            // r uses OLD memory
                ry = fmaf(m.y, wrv, ry);
                m.x = m.x * (1.f - wwv*e2.x) + wwv*a2.x;
                m.y = m.y * (1.f - wwv*e2.y) + wwv*a2.y;
                *mp = m;
            }
            __syncthreads();
            float* racc = sh + 128;                 // [8 warps][64]
            racc[warp*64 + 2*lane]     = rx;
            racc[warp*64 + 2*lane + 1] = ry;
            __syncthreads();
            if (tid < 64) {
                float s = 0.f;
                #pragma unroll
                for (int i = 0; i < 8; ++i) s += racc[i*64 + tid];
                atomicAdd(&g_r[b2*WW + tid], s);
            }
        }
        gridbar();
    }
}

extern "C" void kernel_launch(void* const* d_in, const int* in_sizes, int n_in,
                              void* d_out, int out_size) {
    const float* x  = (const float*)d_in[0];   // (T,B,IN) fp32
    const float* Wc = (const float*)d_in[1];   // (192,332) fp32
    const float* bc = (const float*)d_in[2];   // (332,)   fp32
    ntm_kernel<<<NBLK, NTHR>>>(x, Wc, bc, (float*)d_out);
}

// round 2
// speedup vs baseline: 2.2102x; 2.2102x over previous
#include <cuda_runtime.h>
#include <cuda_bf16.h>

#define TT   32
#define BB   16
#define INS  64
#define OUTS 64
#define LL   4096
#define WW   64
#define CO   332      // OUT + 70 + 198
#define NBLK 128
#define NTHR 256

// ---------------- persistent device state (no allocs allowed) ----------------
// g_mem is TRANSPOSED: [b][w][l]  (l contiguous) -> coalesced, reduction-free
__device__ float g_mem[BB*WW*LL];     // 16 MB memory matrix (transposed)
__device__ float g_wr [BB*LL];        // read weights (normalized, prev step)
__device__ float g_ww [BB*LL];        // write weights
__device__ float g_wcr[BB*LL];        // exp(K*beta - beta) read head
__device__ float g_wcw[BB*LL];        // exp(K*beta - beta) write head
__device__ float g_wur[BB*LL];        // sharpened unnormalized read w
__device__ float g_wuw[BB*LL];        // sharpened unnormalized write w
__device__ float g_coX[TT*BB*CO];     // precomputed x @ Wc[:64] + bc
__device__ float g_params[BB*288];    // per-batch packed params
__device__ float g_out[BB*OUTS];
__device__ float g_r  [BB*WW];
__device__ float g_sums[BB*4];        // [sum_exp_r, sum_exp_w, sum_wr, sum_ww]
__device__ unsigned int g_bar_count = 0;
__device__ unsigned int g_bar_gen   = 0;

__device__ __forceinline__ float softplusf(float x) {
    return (x > 20.f) ? x : log1pf(__expf(x));
}
__device__ __forceinline__ float sigmoidf(float x) {
    return 1.f / (1.f + __expf(-x));
}

// Sense-reversal grid barrier, replay-safe.
__device__ __forceinline__ void gridbar() {
    __syncthreads();
    if (threadIdx.x == 0) {
        __threadfence();
        unsigned int gen  = *(volatile unsigned int*)&g_bar_gen;
        unsigned int prev = atomicAdd(&g_bar_count, 1u);
        if (prev == gridDim.x - 1u) {
            atomicExch(&g_bar_count, 0u);
            __threadfence();
            atomicAdd(&g_bar_gen, 1u);
        } else {
            while (*(volatile unsigned int*)&g_bar_gen == gen) { }
        }
        __threadfence();
    }
    __syncthreads();
}

// Shared layout (floats):
//   [0:128)      keys (ph2) / e|a (ph4)
//   [128:640)    swr  : normalized read w   (ph4 -> next-step ph3 w_prev)
//   [640:1152)   sww  : normalized write w
//   [1152:1664)  sh_er: exp values read head  (ph2 -> ph3)
//   [1664:2176)  sh_ew: exp values write head
//   [2176:2688)  scratch: ph1 (cat/co/scal), ph2/ph3 reductions
#define SH_SWR  128
#define SH_SWW  640
#define SH_ER   1152
#define SH_EW   1664
#define SH_SCR  2176

__global__ __launch_bounds__(NTHR)
void ntm_kernel(const float* __restrict__ x, const float* __restrict__ Wc,
                const float* __restrict__ bc, float* __restrict__ dout)
{
    const int bk   = blockIdx.x;
    const int tid  = threadIdx.x;
    const int gthr = bk * NTHR + tid;
    const int GT   = NBLK * NTHR;
    __shared__ __align__(16) float sh[2688];

    // ---------------- init: zero state + precompute x-part of controller ----
    {
        float4* m4 = (float4*)g_mem;
        for (int i = gthr; i < BB*WW*LL/4; i += GT) m4[i] = make_float4(0,0,0,0);
        for (int i = gthr; i < BB*LL; i += GT) {
            float v = ((i & (LL-1)) == 0) ? 1.f : 0.f;   // delta at l=0
            g_wr[i] = v; g_ww[i] = v;
        }
        if (gthr < BB*OUTS) g_out[gthr] = 0.f;
        if (gthr < BB*WW)   g_r  [gthr] = 0.f;
        for (int idx = gthr; idx < TT*BB*CO; idx += GT) {
            int j  = idx % CO;
            int tb = idx / CO;
            const float* xp = x + tb * INS;
            float acc = bc[j];
            #pragma unroll 8
            for (int i = 0; i < INS; i++) acc = fmaf(xp[i], Wc[i*CO + j], acc);
            g_coX[idx] = acc;
        }
    }

    const int b2   = bk >> 3;           // batch handled in phases 2-4
    const int l0   = (bk & 7) * 512;    // 512-col chunk of L
    const int bl   = b2 * LL;
    const int warp = tid >> 5;
    const int lane = tid & 31;

    // initial w_prev in shared (delta at l==0)
    for (int k = tid; k < 512; k += NTHR) {
        float v = (l0 + k == 0) ? 1.f : 0.f;
        sh[SH_SWR + k] = v; sh[SH_SWW + k] = v;
    }
    gridbar();

    for (int t = 0; t < TT; ++t) {
        // -------- Phase 1: controller + param derivation (blocks 0..15) ----
        if (bk < BB) {
            const int b = bk;
            float* cat  = sh + SH_SCR;          // 128
            float* co   = sh + SH_SCR + 128;    // 332
            float* scal = sh + SH_SCR + 464;    // 16
            if (tid < 64)       cat[tid] = g_out[b*OUTS + tid];
            else if (tid < 128) cat[tid] = __ldcg(&g_r[b*WW + tid - 64]);
            __syncthreads();
            const float* wbase = Wc + INS*CO;   // rows 64..191
            for (int j = tid; j < CO; j += NTHR) {
                float acc = g_coX[(t*BB + b)*CO + j];
                #pragma unroll 16
                for (int i = 0; i < 128; i++)
                    acc = fmaf(cat[i], wbase[i*CO + j], acc);
                co[j] = acc;
            }
            __syncthreads();
            if (warp == 0) {           // ||k_r||^2
                float p = co[64+lane]*co[64+lane] + co[96+lane]*co[96+lane];
                #pragma unroll
                for (int o = 16; o; o >>= 1) p += __shfl_xor_sync(0xffffffffu, p, o);
                if (lane == 0) scal[14] = p;
            } else if (warp == 1) {    // ||k_w||^2
                float p = co[134+lane]*co[134+lane] + co[166+lane]*co[166+lane];
                #pragma unroll
                for (int o = 16; o; o >>= 1) p += __shfl_xor_sync(0xffffffffu, p, o);
                if (lane == 0) scal[15] = p;
            }
            __syncthreads();
            float* P = g_params + b*288;
            if (tid == 0) {
                float beta_r = softplusf(co[128]);
                float beta_w = softplusf(co[198]);
                scal[0] = beta_r * rsqrtf(scal[14] + 1e-14f);
                scal[1] = beta_w * rsqrtf(scal[15] + 1e-14f);
                P[128] = beta_r;
                P[129] = sigmoidf(co[129]);
                P[130] = softplusf(co[130]) + 1.f;
                float m = fmaxf(co[131], fmaxf(co[132], co[133]));
                float e0=__expf(co[131]-m), e1=__expf(co[132]-m), e2=__expf(co[133]-m);
                float inv = 1.f/(e0+e1+e2);
                P[131]=e0*inv; P[132]=e1*inv; P[133]=e2*inv;
                P[134] = beta_w;
                P[135] = sigmoidf(co[199]);
                P[136] = softplusf(co[200]) + 1.f;
                m = fmaxf(co[201], fmaxf(co[202], co[203]));
                e0=__expf(co[201]-m); e1=__expf(co[202]-m); e2=__expf(co[203]-m);
                inv = 1.f/(e0+e1+e2);
                P[137]=e0*inv; P[138]=e1*inv; P[139]=e2*inv;
            }
            __syncthreads();
            if (tid < 64) {
                P[tid]       = co[64 + tid]  * scal[0];   // k_r * beta/||k_r||
                P[64 + tid]  = co[134 + tid] * scal[1];   // k_w * beta/||k_w||
                P[140 + tid] = sigmoidf(co[204 + tid]);   // e
                P[204 + tid] = co[268 + tid];             // a
                float o = co[tid];
                g_out[b*OUTS + tid] = o;
                dout[(t*BB + b)*OUTS + tid] = o;
                g_r[b*WW + tid] = 0.f;
            }
            if (tid < 4) g_sums[b*4 + tid] = 0.f;
        }
        gridbar();

        // -------- Phase 2: cosine similarity (reduction-free, transposed) --
        {
            const float* P = g_params + b2*288;
            if (tid < 128) sh[tid] = __ldcg(&P[tid]);    // kr|kw (pre-scaled)
            __syncthreads();
            const float beta_r = __ldcg(&P[128]);
            const float beta_w = __ldcg(&P[134]);
            const int l = 2*tid;
            const float* mcol = g_mem + (size_t)(b2*WW)*LL + l0 + l;
            float dr0=0,dr1=0,dw0=0,dw1=0,ds0=0,ds1=0;
            #pragma unroll 8
            for (int w = 0; w < WW; ++w) {
                float2 m = *(const float2*)(mcol + (size_t)w*LL);
                float kr = sh[w], kw = sh[64+w];
                dr0 = fmaf(m.x,kr,dr0);  dr1 = fmaf(m.y,kr,dr1);
                dw0 = fmaf(m.x,kw,dw0);  dw1 = fmaf(m.y,kw,dw1);
                ds0 = fmaf(m.x,m.x,ds0); ds1 = fmaf(m.y,m.y,ds1);
            }
            const float inm0 = rsqrtf(ds0 + 1e-14f);
            const float inm1 = rsqrtf(ds1 + 1e-14f);
            // softmax shifted by beta: arg in [-2*beta, 0], overflow-safe
            const float er0 = __expf(dr0*inm0 - beta_r);
            const float er1 = __expf(dr1*inm1 - beta_r);
            const float ew0 = __expf(dw0*inm0 - beta_w);
            const float ew1 = __expf(dw1*inm1 - beta_w);
            sh[SH_ER + l] = er0; sh[SH_ER + l + 1] = er1;
            sh[SH_EW + l] = ew0; sh[SH_EW + l + 1] = ew1;
            *(float2*)&g_wcr[bl + l0 + l] = make_float2(er0, er1);
            *(float2*)&g_wcw[bl + l0 + l] = make_float2(ew0, ew1);
            float s_er = er0 + er1, s_ew = ew0 + ew1;
            #pragma unroll
            for (int o = 16; o; o >>= 1) {
                s_er += __shfl_xor_sync(0xffffffffu, s_er, o);
                s_ew += __shfl_xor_sync(0xffffffffu, s_ew, o);
            }
            if (lane == 0) { sh[SH_SCR + warp] = s_er; sh[SH_SCR + 8 + warp] = s_ew; }
            __syncthreads();
            if (tid == 0) {
                float a = 0.f, c = 0.f;
                #pragma unroll
                for (int i = 0; i < 8; ++i) { a += sh[SH_SCR+i]; c += sh[SH_SCR+8+i]; }
                atomicAdd(&g_sums[b2*4 + 0], a);
                atomicAdd(&g_sums[b2*4 + 1], c);
            }
        }
        gridbar();

        // -------- Phase 3: gate + circular shift + sharpen -----------------
        {
            const float* P = g_params + b2*288;
            const float inv_ser = 1.f / __ldcg(&g_sums[b2*4 + 0]);
            const float inv_sew = 1.f / __ldcg(&g_sums[b2*4 + 1]);
            const float gr  = __ldcg(&P[129]), gamr = __ldcg(&P[130]);
            const float sr0 = __ldcg(&P[131]), sr1 = __ldcg(&P[132]), sr2 = __ldcg(&P[133]);
            const float gw  = __ldcg(&P[135]), gamw = __ldcg(&P[136]);
            const float sw0 = __ldcg(&P[137]), sw1 = __ldcg(&P[138]), sw2 = __ldcg(&P[139]);
            const int lm_g = bl + ((l0 + LL - 1) & (LL - 1));   // left halo index
            const int lp_g = bl + ((l0 + 512)    & (LL - 1));   // right halo index
            float ps_r = 0.f, ps_w = 0.f;
            #pragma unroll
            for (int kk = 0; kk < 2; ++kk) {
                const int k  = tid + kk*256;
                const int lc = bl + l0 + k;
                // read head
                float cm = (k > 0)   ? sh[SH_ER + k - 1] : __ldcg(&g_wcr[lm_g]);
                float cc = sh[SH_ER + k];
                float cp = (k < 511) ? sh[SH_ER + k + 1] : __ldcg(&g_wcr[lp_g]);
                float pm = (k > 0)   ? sh[SH_SWR + k - 1] : __ldcg(&g_wr[lm_g]);
                float pc = sh[SH_SWR + k];
                float pp = (k < 511) ? sh[SH_SWR + k + 1] : __ldcg(&g_wr[lp_g]);
                float wgm = cm*inv_ser*gr + (1.f-gr)*pm;
                float wgc = cc*inv_ser*gr + (1.f-gr)*pc;
                float wgp = cp*inv_ser*gr + (1.f-gr)*pp;
                float wu  = powf(fmaxf(sr0*wgm + sr1*wgc + sr2*wgp, 0.f), gamr);
                g_wur[lc] = wu; ps_r += wu;
                // write head
                cm = (k > 0)   ? sh[SH_EW + k - 1] : __ldcg(&g_wcw[lm_g]);
                cc = sh[SH_EW + k];
                cp = (k < 511) ? sh[SH_EW + k + 1] : __ldcg(&g_wcw[lp_g]);
                pm = (k > 0)   ? sh[SH_SWW + k - 1] : __ldcg(&g_ww[lm_g]);
                pc = sh[SH_SWW + k];
                pp = (k < 511) ? sh[SH_SWW + k + 1] : __ldcg(&g_ww[lp_g]);
                wgm = cm*inv_sew*gw + (1.f-gw)*pm;
                wgc = cc*inv_sew*gw + (1.f-gw)*pc;
                wgp = cp*inv_sew*gw + (1.f-gw)*pp;
                wu  = powf(fmaxf(sw0*wgm + sw1*wgc + sw2*wgp, 0.f), gamw);
                g_wuw[lc] = wu; ps_w += wu;
            }
            #pragma unroll
            for (int o = 16; o; o >>= 1) {
                ps_r += __shfl_xor_sync(0xffffffffu, ps_r, o);
                ps_w += __shfl_xor_sync(0xffffffffu, ps_w, o);
            }
            if (lane == 0) { sh[SH_SCR + warp] = ps_r; sh[SH_SCR + 8 + warp] = ps_w; }
            __syncthreads();
            if (tid == 0) {
                float a = 0.f, c = 0.f;
                #pragma unroll
                for (int i = 0; i < 8; ++i) { a += sh[SH_SCR+i]; c += sh[SH_SCR+8+i]; }
                atomicAdd(&g_sums[b2*4 + 2], a);
                atomicAdd(&g_sums[b2*4 + 3], c);
            }
        }
        gridbar();

        // -------- Phase 4: read vector + erase/add memory update -----------
        {
            const float inv_sr = 1.f / __ldcg(&g_sums[b2*4 + 2]);
            const float inv_sw = 1.f / __ldcg(&g_sums[b2*4 + 3]);
            if (tid < 128) sh[tid] = __ldcg(&g_params[b2*288 + 140 + tid]); // e|a
            // normalize weights -> shared (w_prev for next step) + global
            for (int k = tid; k < 512; k += NTHR) {
                float wrv = g_wur[bl + l0 + k] * inv_sr;
                float wwv = g_wuw[bl + l0 + k] * inv_sw;
                sh[SH_SWR + k] = wrv; sh[SH_SWW + k] = wwv;
                g_wr[bl + l0 + k] = wrv; g_ww[bl + l0 + k] = wwv;
            }
            __syncthreads();
            const float4* wr4 = (const float4*)(sh + SH_SWR);
            const float4* ww4 = (const float4*)(sh + SH_SWW);
            #pragma unroll
            for (int i = 0; i < 8; ++i) {
                const int w = warp*8 + i;
                const float e = sh[w], a = sh[64 + w];
                float4* mp = (float4*)(g_mem + (size_t)(b2*WW + w)*LL + l0);
                float racc = 0.f;
                #pragma unroll
                for (int j = lane; j < 128; j += 32) {
                    float4 m = mp[j];
                    float4 r = wr4[j];
                    float4 q = ww4[j];
                    racc += m.x*r.x + m.y*r.y + m.z*r.z + m.w*r.w;  // OLD memory
                    m.x = m.x*(1.f - q.x*e) + q.x*a;
                    m.y = m.y*(1.f - q.y*e) + q.y*a;
                    m.z = m.z*(1.f - q.z*e) + q.z*a;
                    m.w = m.w*(1.f - q.w*e) + q.w*a;
                    mp[j] = m;
                }
                #pragma unroll
                for (int o = 16; o; o >>= 1) racc += __shfl_xor_sync(0xffffffffu, racc, o);
                if (lane == 0) atomicAdd(&g_r[b2*WW + w], racc);
            }
        }
        gridbar();
    }
}

extern "C" void kernel_launch(void* const* d_in, const int* in_sizes, int n_in,
                              void* d_out, int out_size) {
    const float* x  = (const float*)d_in[0];   // (T,B,IN) fp32
    const float* Wc = (const float*)d_in[1];   // (192,332) fp32
    const float* bc = (const float*)d_in[2];   // (332,)   fp32
    ntm_kernel<<<NBLK, NTHR>>>(x, Wc, bc, (float*)d_out);
}

// round 4
// speedup vs baseline: 3.0813x; 1.3941x over previous
#include <cuda_runtime.h>
#include <cuda_bf16.h>

#define TT   32
#define BB   16
#define INS  64
#define OUTS 64
#define LL   4096
#define WW   64
#define CO   332      // OUT + 70 + 198
#define NBLK 128
#define NTHR 512
#define CHUNK 512     // L-columns per block

// ---- smem layout (floats) ----
#define S_MEM 0          // 64*512 = 32768   memory slice [w][l]
#define S_SWR 32768      // 512  normalized read w (w_prev)
#define S_SWW 33280      // 512  normalized write w
#define S_ER  33792      // 512  exp read
#define S_EW  34304      // 512  exp write
#define S_WUR 34816      // 512  sharpened unnorm read
#define S_WUW 35328      // 512  sharpened unnorm write
#define S_EA  35840      // 128  keys (ph2) / e|a (ph4)
#define S_SCR 35968      // 512  ph1 cat(128)+co(332)+scal; reductions
#define S_TOT 36480      // floats -> 145920 bytes

// ---------------- persistent device state ----------------
__device__ float g_wr [BB*LL];        // only halo elements actually consumed
__device__ float g_ww [BB*LL];
__device__ float g_wcr[BB*LL];
__device__ float g_wcw[BB*LL];
__device__ float g_coX[BB*TT*CO];     // [b][t][332] precomputed x@Wc + bc
__device__ float g_params[BB*288];
__device__ float g_out[BB*OUTS];
__device__ float g_r  [BB*WW];
__device__ float g_sums[BB*32];       // per-batch, padded to 128B
__device__ unsigned int g_bcnt[BB*32];
__device__ unsigned int g_bgen[BB*32];

__device__ __forceinline__ float softplusf(float x) {
    return (x > 20.f) ? x : log1pf(__expf(x));
}
__device__ __forceinline__ float sigmoidf(float x) {
    return 1.f / (1.f + __expf(-x));
}

// 8-block group barrier, sense-reversal, replay-safe, polite spin.
__device__ __forceinline__ void groupbar(int grp) {
    __syncthreads();
    if (threadIdx.x == 0) {
        __threadfence();                                   // release
        const int idx = grp * 32;
        unsigned int gen  = *(volatile unsigned int*)&g_bgen[idx];
        unsigned int prev = atomicAdd(&g_bcnt[idx], 1u);
        if (prev == 7u) {
            atomicExch(&g_bcnt[idx], 0u);
            __threadfence();
            atomicAdd(&g_bgen[idx], 1u);
        } else {
            while (*(volatile unsigned int*)&g_bgen[idx] == gen) {
                __nanosleep(64);
            }
        }
        __threadfence();                                   // acquire
    }
    __syncthreads();
}

__global__ __launch_bounds__(NTHR)
void ntm_kernel(const float* __restrict__ x, const float* __restrict__ Wc,
                const float* __restrict__ bc, float* __restrict__ dout)
{
    extern __shared__ __align__(16) float sh[];
    const int bk    = blockIdx.x;
    const int tid   = threadIdx.x;
    const int b     = bk >> 3;           // batch (group id)
    const int chunk = bk & 7;
    const int l0    = chunk * CHUNK;
    const int bl    = b * LL;
    const int warp  = tid >> 5;
    const int lane  = tid & 31;
    const bool leader = (chunk == 0);

    // ---------------- init (all group-local) ----------------
    {
        float4* m4 = (float4*)(sh + S_MEM);
        for (int i = tid; i < WW*CHUNK/4; i += NTHR) m4[i] = make_float4(0,0,0,0);
        for (int k = tid; k < CHUNK; k += NTHR) {
            float v = (l0 + k == 0) ? 1.f : 0.f;
            sh[S_SWR + k] = v; sh[S_SWW + k] = v;
        }
        if (tid == 0) {   // halo sources for neighbors
            __stcg(&g_wr[bl + l0],          (l0 == 0) ? 1.f : 0.f);
            __stcg(&g_wr[bl + l0 + 511],    0.f);
            __stcg(&g_ww[bl + l0],          (l0 == 0) ? 1.f : 0.f);
            __stcg(&g_ww[bl + l0 + 511],    0.f);
        }
        if (leader) {
            if (tid < 64) { g_out[b*OUTS + tid] = 0.f; g_r[b*WW + tid] = 0.f; }
            if (tid < 4)  g_sums[b*32 + tid] = 0.f;
        }
        // coX for this batch: 32*332 entries split across 8 blocks
        const int per = (TT*CO + 7) / 8;          // 1328
        for (int idx = chunk*per + tid; idx < min((chunk+1)*per, TT*CO); idx += NTHR) {
            const int t = idx / CO, j = idx % CO;
            const float* xp = x + (t*BB + b) * INS;
            float acc = bc[j];
            #pragma unroll 8
            for (int i = 0; i < INS; i++) acc = fmaf(xp[i], Wc[i*CO + j], acc);
            g_coX[(b*TT + t)*CO + j] = acc;
        }
    }
    groupbar(b);

    for (int t = 0; t < TT; ++t) {
        // -------- Phase 1: controller + params (leader only) --------------
        if (leader) {
            float* cat  = sh + S_SCR;          // 128
            float* co   = sh + S_SCR + 128;    // 332
            float* scal = sh + S_SCR + 464;    // 16
            if (tid < 64)       cat[tid] = g_out[b*OUTS + tid];
            else if (tid < 128) cat[tid] = __ldcg(&g_r[b*WW + tid - 64]);
            __syncthreads();
            if (tid < CO) {
                const float* wbase = Wc + INS*CO;
                float acc = __ldcg(&g_coX[(b*TT + t)*CO + tid]);
                #pragma unroll 16
                for (int i = 0; i < 128; i++)
                    acc = fmaf(cat[i], __ldg(&wbase[i*CO + tid]), acc);
                co[tid] = acc;
            }
            __syncthreads();
            if (warp == 0) {           // ||k_r||^2
                float p = co[64+lane]*co[64+lane] + co[96+lane]*co[96+lane];
                #pragma unroll
                for (int o = 16; o; o >>= 1) p += __shfl_xor_sync(0xffffffffu, p, o);
                if (lane == 0) scal[14] = p;
            } else if (warp == 1) {    // ||k_w||^2
                float p = co[134+lane]*co[134+lane] + co[166+lane]*co[166+lane];
                #pragma unroll
                for (int o = 16; o; o >>= 1) p += __shfl_xor_sync(0xffffffffu, p, o);
                if (lane == 0) scal[15] = p;
            }
            __syncthreads();
            float* P = g_params + b*288;
            if (tid == 0) {
                float beta_r = softplusf(co[128]);
                float beta_w = softplusf(co[198]);
                scal[0] = beta_r * rsqrtf(scal[14] + 1e-14f);
                scal[1] = beta_w * rsqrtf(scal[15] + 1e-14f);
                P[128] = beta_r;
                P[129] = sigmoidf(co[129]);
                P[130] = softplusf(co[130]) + 1.f;
                float m = fmaxf(co[131], fmaxf(co[132], co[133]));
                float e0=__expf(co[131]-m), e1=__expf(co[132]-m), e2=__expf(co[133]-m);
                float inv = 1.f/(e0+e1+e2);
                P[131]=e0*inv; P[132]=e1*inv; P[133]=e2*inv;
                P[134] = beta_w;
                P[135] = sigmoidf(co[199]);
                P[136] = softplusf(co[200]) + 1.f;
                m = fmaxf(co[201], fmaxf(co[202], co[203]));
                e0=__expf(co[201]-m); e1=__expf(co[202]-m); e2=__expf(co[203]-m);
                inv = 1.f/(e0+e1+e2);
                P[137]=e0*inv; P[138]=e1*inv; P[139]=e2*inv;
            }
            __syncthreads();
            if (tid < 64) {
                P[tid]       = co[64 + tid]  * scal[0];   // k_r * beta/||k_r||
                P[64 + tid]  = co[134 + tid] * scal[1];   // k_w * beta/||k_w||
                P[140 + tid] = sigmoidf(co[204 + tid]);   // e
                P[204 + tid] = co[268 + tid];             // a
                float o = co[tid];
                g_out[b*OUTS + tid] = o;
                dout[(t*BB + b)*OUTS + tid] = o;
                g_r[b*WW + tid] = 0.f;
            }
            if (tid < 4) g_sums[b*32 + tid] = 0.f;
        }
        groupbar(b);

        // -------- Phase 2: cosine similarity (smem, reduction-free) -------
        {
            const float* P = g_params + b*288;
            if (tid < 128)       sh[S_EA + tid]  = __ldcg(&P[tid]);   // keys
            else if (tid == 128) sh[S_SCR + 40] = __ldcg(&P[128]);    // beta_r
            else if (tid == 129) sh[S_SCR + 41] = __ldcg(&P[134]);    // beta_w
            __syncthreads();
            const float beta_r = sh[S_SCR + 40];
            const float beta_w = sh[S_SCR + 41];
            const int l = tid;
            float dr = 0.f, dw = 0.f, ds = 0.f;
            #pragma unroll 16
            for (int w = 0; w < WW; ++w) {
                const float m  = sh[S_MEM + w*CHUNK + l];
                dr = fmaf(m, sh[S_EA + w],      dr);
                dw = fmaf(m, sh[S_EA + 64 + w], dw);
                ds = fmaf(m, m,                 ds);
            }
            const float inm = rsqrtf(ds + 1e-14f);
            const float er = __expf(dr*inm - beta_r);   // arg in [-2b, 0]
            const float ew = __expf(dw*inm - beta_w);
            sh[S_ER + l] = er; sh[S_EW + l] = ew;
            if (l == 0 || l == CHUNK-1) {               // halo for neighbors
                __stcg(&g_wcr[bl + l0 + l], er);
                __stcg(&g_wcw[bl + l0 + l], ew);
            }
            float s_er = er, s_ew = ew;
            #pragma unroll
            for (int o = 16; o; o >>= 1) {
                s_er += __shfl_xor_sync(0xffffffffu, s_er, o);
                s_ew += __shfl_xor_sync(0xffffffffu, s_ew, o);
            }
            if (lane == 0) { sh[S_SCR + warp] = s_er; sh[S_SCR + 16 + warp] = s_ew; }
            __syncthreads();
            if (tid == 0) {
                float a = 0.f, c = 0.f;
                #pragma unroll
                for (int i = 0; i < 16; ++i) { a += sh[S_SCR+i]; c += sh[S_SCR+16+i]; }
                atomicAdd(&g_sums[b*32 + 0], a);
                atomicAdd(&g_sums[b*32 + 1], c);
            }
        }
        groupbar(b);

        // -------- Phase 3: gate + shift + sharpen (smem) -------------------
        {
            const float* P = g_params + b*288;
            const float inv_ser = 1.f / __ldcg(&g_sums[b*32 + 0]);
            const float inv_sew = 1.f / __ldcg(&g_sums[b*32 + 1]);
            const float gr  = __ldcg(&P[129]), gamr = __ldcg(&P[130]);
            const float sr0 = __ldcg(&P[131]), sr1 = __ldcg(&P[132]), sr2 = __ldcg(&P[133]);
            const float gw  = __ldcg(&P[135]), gamw = __ldcg(&P[136]);
            const float sw0 = __ldcg(&P[137]), sw1 = __ldcg(&P[138]), sw2 = __ldcg(&P[139]);
            const int lm_g = bl + ((l0 + LL - 1)    & (LL - 1));
            const int lp_g = bl + ((l0 + CHUNK)     & (LL - 1));
            const int k = tid;
            // read head
            float cm = (k > 0)        ? sh[S_ER + k - 1] : __ldcg(&g_wcr[lm_g]);
            float cc = sh[S_ER + k];
            float cp = (k < CHUNK-1)  ? sh[S_ER + k + 1] : __ldcg(&g_wcr[lp_g]);
            float pm = (k > 0)        ? sh[S_SWR + k - 1] : __ldcg(&g_wr[lm_g]);
            float pc = sh[S_SWR + k];
            float pp = (k < CHUNK-1)  ? sh[S_SWR + k + 1] : __ldcg(&g_wr[lp_g]);
            float wgm = cm*inv_ser*gr + (1.f-gr)*pm;
            float wgc = cc*inv_ser*gr + (1.f-gr)*pc;
            float wgp = cp*inv_ser*gr + (1.f-gr)*pp;
            float wur = powf(fmaxf(sr0*wgm + sr1*wgc + sr2*wgp, 0.f), gamr);
            sh[S_WUR + k] = wur;
            // write head
            cm = (k > 0)       ? sh[S_EW + k - 1] : __ldcg(&g_wcw[lm_g]);
            cc = sh[S_EW + k];
            cp = (k < CHUNK-1) ? sh[S_EW + k + 1] : __ldcg(&g_wcw[lp_g]);
            pm = (k > 0)       ? sh[S_SWW + k - 1] : __ldcg(&g_ww[lm_g]);
            pc = sh[S_SWW + k];
            pp = (k < CHUNK-1) ? sh[S_SWW + k + 1] : __ldcg(&g_ww[lp_g]);
            wgm = cm*inv_sew*gw + (1.f-gw)*pm;
            wgc = cc*inv_sew*gw + (1.f-gw)*pc;
            wgp = cp*inv_sew*gw + (1.f-gw)*pp;
            float wuw = powf(fmaxf(sw0*wgm + sw1*wgc + sw2*wgp, 0.f), gamw);
            sh[S_WUW + k] = wuw;
            float ps_r = wur, ps_w = wuw;
            #pragma unroll
            for (int o = 16; o; o >>= 1) {
                ps_r += __shfl_xor_sync(0xffffffffu, ps_r, o);
                ps_w += __shfl_xor_sync(0xffffffffu, ps_w, o);
            }
            if (lane == 0) { sh[S_SCR + warp] = ps_r; sh[S_SCR + 16 + warp] = ps_w; }
            __syncthreads();
            if (tid == 0) {
                float a = 0.f, c = 0.f;
                #pragma unroll
                for (int i = 0; i < 16; ++i) { a += sh[S_SCR+i]; c += sh[S_SCR+16+i]; }
                atomicAdd(&g_sums[b*32 + 2], a);
                atomicAdd(&g_sums[b*32 + 3], c);
            }
        }
        groupbar(b);

        // -------- Phase 4: normalize + read vector + memory update ---------
        {
            const float inv_sr = 1.f / __ldcg(&g_sums[b*32 + 2]);
            const float inv_sw = 1.f / __ldcg(&g_sums[b*32 + 3]);
            if (tid < 128) sh[S_EA + tid] = __ldcg(&g_params[b*288 + 140 + tid]); // e|a
            {
                const int k = tid;
                float wrv = sh[S_WUR + k] * inv_sr;
                float wwv = sh[S_WUW + k] * inv_sw;
                sh[S_SWR + k] = wrv; sh[S_SWW + k] = wwv;
                if (k == 0 || k == CHUNK-1) {
                    __stcg(&g_wr[bl + l0 + k], wrv);
                    __stcg(&g_ww[bl + l0 + k], wwv);
                }
            }
            __syncthreads();
            const float4* wr4 = (const float4*)(sh + S_SWR);
            const float4* ww4 = (const float4*)(sh + S_SWW);
            #pragma unroll
            for (int i = 0; i < 4; ++i) {
                const int w = warp*4 + i;
                const float e = sh[S_EA + w], a = sh[S_EA + 64 + w];
                float4* mp = (float4*)(sh + S_MEM + w*CHUNK);
                float racc = 0.f;
                #pragma unroll
                for (int j = lane; j < CHUNK/4; j += 32) {
                    float4 m = mp[j];
                    float4 r = wr4[j];
                    float4 q = ww4[j];
                    racc += m.x*r.x + m.y*r.y + m.z*r.z + m.w*r.w;   // OLD memory
                    m.x = m.x*(1.f - q.x*e) + q.x*a;
                    m.y = m.y*(1.f - q.y*e) + q.y*a;
                    m.z = m.z*(1.f - q.z*e) + q.z*a;
                    m.w = m.w*(1.f - q.w*e) + q.w*a;
                    mp[j] = m;
                }
                #pragma unroll
                for (int o = 16; o; o >>= 1) racc += __shfl_xor_sync(0xffffffffu, racc, o);
                if (lane == 0) atomicAdd(&g_r[b*WW + w], racc);
            }
        }
        groupbar(b);
    }
}

extern "C" void kernel_launch(void* const* d_in, const int* in_sizes, int n_in,
                              void* d_out, int out_size) {
    const float* x  = (const float*)d_in[0];   // (T,B,IN) fp32
    const float* Wc = (const float*)d_in[1];   // (192,332) fp32
    const float* bc = (const float*)d_in[2];   // (332,)   fp32
    static bool attr_done = false;             // host-side only; kernel work is
    if (!attr_done) {                          // identical on every call
        cudaFuncSetAttribute(ntm_kernel, cudaFuncAttributeMaxDynamicSharedMemorySize,
                             S_TOT * sizeof(float));
        attr_done = true;
    }
    ntm_kernel<<<NBLK, NTHR, S_TOT * sizeof(float)>>>(x, Wc, bc, (float*)d_out);
}